// round 1
// baseline (speedup 1.0000x reference)
#include <cuda_runtime.h>
#include <math.h>

// Problem constants (fixed shapes from reference): B=2, N=512, C=128, BC=64
#define NB 2
#define NN 512
#define NC 128
#define O1 128
#define O2 64
#define JC 64            // j-chunk per iteration
#define KEEPK 460        // int(512*0.9)
#define DROPK 52         // 512 - 460

// Folded weights (BN folded in), produced by prelude kernel.
__device__ float g_W1tf[NC * O1];   // [c][o]  : W1[o][c]*s1[o]
__device__ float g_W2tf[O1 * O2];   // [k][n]  : W2[n][k]*s2[n]
__device__ float g_b1f[O1];
__device__ float g_b2f[O2];
__device__ float g_W3f[O2];
__device__ float g_b3f;

__global__ void prelude_kernel(
    const float* __restrict__ W1, const float* __restrict__ g1,
    const float* __restrict__ be1, const float* __restrict__ m1,
    const float* __restrict__ v1,
    const float* __restrict__ W2, const float* __restrict__ g2,
    const float* __restrict__ be2, const float* __restrict__ m2,
    const float* __restrict__ v2,
    const float* __restrict__ W3, const float* __restrict__ b3)
{
    __shared__ float s1[O1], s2[O2];
    int t = threadIdx.x;
    if (t < O1) {
        float s = g1[t] / sqrtf(v1[t] + 1e-5f);
        s1[t] = s;
        g_b1f[t] = be1[t] - m1[t] * s;
    } else if (t < O1 + O2) {
        int o = t - O1;
        float s = g2[o] / sqrtf(v2[o] + 1e-5f);
        s2[o] = s;
        g_b2f[o] = be2[o] - m2[o] * s;
    } else if (t < O1 + 2 * O2) {
        int o = t - (O1 + O2);
        g_W3f[o] = W3[o];
        if (o == 0) g_b3f = b3[0];
    }
    __syncthreads();
    for (int idx = t; idx < NC * O1; idx += blockDim.x) {
        int o = idx & (O1 - 1);
        int c = idx >> 7;
        g_W1tf[idx] = W1[o * NC + c] * s1[o];
    }
    for (int idx = t; idx < O1 * O2; idx += blockDim.x) {
        int n = idx & (O2 - 1);
        int k = idx >> 6;
        g_W2tf[idx] = W2[n * O1 + k] * s2[n];
    }
}

// SMEM layout (floats)
#define SM_W1   0
#define SM_W2   (SM_W1 + NC * O1)            // 16384
#define SM_DS   (SM_W2 + O1 * O2)            // +8192
#define DS_STR  65
#define SM_H1   (SM_DS + NC * DS_STR)        // +8320
#define H1_STR  65
#define SM_VI   (SM_H1 + O1 * H1_STR)        // +8320
#define SM_RED  (SM_VI + NC)                 // +128
#define RED_STR 65
#define SM_NSS  (SM_RED + 16 * RED_STR)      // +1040
#define SM_B1   (SM_NSS + JC)                // +64
#define SM_B2   (SM_B1 + O1)                 // +128
#define SM_W3   (SM_B2 + O2)                 // +64
#define SM_TOTF (SM_W3 + O2)                 // total floats
#define SMEM_A_BYTES (SM_TOTF * 4)

__global__ void __launch_bounds__(256, 1) mlp_kernel(
    const float* __restrict__ vp,       // [B,N,C]
    const float* __restrict__ epl,      // [B,N,N]
    float* __restrict__ out_ep,         // [B,N,N] (raw: sigmoid(logit)*ep_last)
    float* __restrict__ out_ns)         // [B,N,N]
{
    extern __shared__ float sm[];
    const int row = blockIdx.x;         // 0..B*N-1
    const int b = row >> 9;
    const int i = row & (NN - 1);
    const int tid = threadIdx.x;

    float* W1s = sm + SM_W1;
    float* W2s = sm + SM_W2;
    float* Ds  = sm + SM_DS;
    float* H1s = sm + SM_H1;
    float* vis = sm + SM_VI;
    float* red = sm + SM_RED;
    float* nss = sm + SM_NSS;
    float* b1s = sm + SM_B1;
    float* b2s = sm + SM_B2;
    float* w3s = sm + SM_W3;

    // Stage weights once per block
    for (int idx = tid; idx < NC * O1; idx += 256) W1s[idx] = g_W1tf[idx];
    for (int idx = tid; idx < O1 * O2; idx += 256) W2s[idx] = g_W2tf[idx];
    if (tid < O1) {
        b1s[tid] = g_b1f[tid];
        vis[tid] = vp[(b * NN + i) * NC + tid];
    } else if (tid < O1 + O2) {
        int o = tid - O1;
        b2s[o] = g_b2f[o];
        w3s[o] = g_W3f[o];
    }

    const int ni  = tid & 15;   // GEMM1: 8 outputs o = ni*8..
    const int mi  = tid >> 4;   // GEMM1: 4 j's    m = mi*4..
    const int ni2 = tid & 15;   // GEMM2: 4 outputs n = ni2*4..
    const int mi2 = tid >> 4;   // GEMM2: 4 j's    m = mi2*4..

    const long rowbase = (long)row * NN;
    const float b3f = g_b3f;

    for (int jc = 0; jc < NN / JC; jc++) {
        const int j0 = jc * JC;
        __syncthreads();  // previous-chunk epilogue done; Ds/H1s/red/nss free

        // Build Ds[c][j] = (vi[c]-vj[c])^2
        #pragma unroll
        for (int t = 0; t < (JC * NC) / 256; t++) {
            int idx = t * 256 + tid;
            int j = idx >> 7;
            int c = idx & (NC - 1);
            float v = vp[(b * NN + j0 + j) * NC + c];
            float d = vis[c] - v;
            Ds[c * DS_STR + j] = d * d;
        }
        __syncthreads();

        // ---- GEMM1: H1[j][o] = leaky( D[j][:] . W1t[:][o] + b1 ) ----
        float acc[4][8];
        #pragma unroll
        for (int m = 0; m < 4; m++)
            #pragma unroll
            for (int n = 0; n < 8; n++)
                acc[m][n] = b1s[ni * 8 + n];

        #pragma unroll 4
        for (int k = 0; k < NC; k++) {
            const float* dsr = &Ds[k * DS_STR + mi * 4];
            float a0 = dsr[0], a1 = dsr[1], a2 = dsr[2], a3 = dsr[3];
            float4 bA = *(const float4*)&W1s[k * O1 + ni * 8];
            float4 bB = *(const float4*)&W1s[k * O1 + ni * 8 + 4];
            float bv[8] = {bA.x, bA.y, bA.z, bA.w, bB.x, bB.y, bB.z, bB.w};
            #pragma unroll
            for (int n = 0; n < 8; n++) {
                acc[0][n] = fmaf(a0, bv[n], acc[0][n]);
                acc[1][n] = fmaf(a1, bv[n], acc[1][n]);
                acc[2][n] = fmaf(a2, bv[n], acc[2][n]);
                acc[3][n] = fmaf(a3, bv[n], acc[3][n]);
            }
        }
        // epilogue: leaky, store K-major H1s[o][j]
        #pragma unroll
        for (int n = 0; n < 8; n++) {
            int o = ni * 8 + n;
            #pragma unroll
            for (int m = 0; m < 4; m++) {
                float x = acc[m][n];
                x = (x > 0.f) ? x : 0.01f * x;
                H1s[o * H1_STR + mi * 4 + m] = x;
            }
        }
        __syncthreads();

        // ---- GEMM2 + layer3 fold ----
        float acc2[4][4];
        #pragma unroll
        for (int m = 0; m < 4; m++)
            #pragma unroll
            for (int n = 0; n < 4; n++)
                acc2[m][n] = b2s[ni2 * 4 + n];

        #pragma unroll 4
        for (int k = 0; k < O1; k++) {
            const float* h1r = &H1s[k * H1_STR + mi2 * 4];
            float a0 = h1r[0], a1 = h1r[1], a2 = h1r[2], a3 = h1r[3];
            float4 bb = *(const float4*)&W2s[k * O2 + ni2 * 4];
            float bv[4] = {bb.x, bb.y, bb.z, bb.w};
            #pragma unroll
            for (int n = 0; n < 4; n++) {
                acc2[0][n] = fmaf(a0, bv[n], acc2[0][n]);
                acc2[1][n] = fmaf(a1, bv[n], acc2[1][n]);
                acc2[2][n] = fmaf(a2, bv[n], acc2[2][n]);
                acc2[3][n] = fmaf(a3, bv[n], acc2[3][n]);
            }
        }
        // leaky + dot with W3 -> partial logits
        float lp[4] = {0.f, 0.f, 0.f, 0.f};
        #pragma unroll
        for (int n = 0; n < 4; n++) {
            float wn = w3s[ni2 * 4 + n];
            #pragma unroll
            for (int m = 0; m < 4; m++) {
                float x = acc2[m][n];
                x = (x > 0.f) ? x : 0.01f * x;
                lp[m] = fmaf(x, wn, lp[m]);
            }
        }
        #pragma unroll
        for (int m = 0; m < 4; m++)
            red[ni2 * RED_STR + mi2 * 4 + m] = lp[m];

        // node similarity partial: column sums of Ds
        if (tid < JC) {
            float s = 0.f;
            #pragma unroll 8
            for (int c = 0; c < NC; c++) s += Ds[c * DS_STR + tid];
            nss[tid] = s;
        }
        __syncthreads();

        // epilogue: reduce logits, sigmoid, * ep_last, write
        if (tid < JC) {
            float lg = b3f;
            #pragma unroll
            for (int g = 0; g < 16; g++) lg += red[g * RED_STR + tid];
            float sg = 1.f / (1.f + expf(-lg));
            int jg = j0 + tid;
            float el = epl[rowbase + jg];
            if (jg == i) el = 0.f;
            out_ep[rowbase + jg] = sg * el;
            out_ns[rowbase + jg] = -nss[tid];
        }
    }
}

// ---------------- Kernel B: per-row top-k + normalize ----------------

__device__ __forceinline__ float blockSum512(float v, float* redsm) {
    #pragma unroll
    for (int o = 16; o > 0; o >>= 1) v += __shfl_xor_sync(0xffffffffu, v, o);
    int w = threadIdx.x >> 5;
    __syncthreads();
    if ((threadIdx.x & 31) == 0) redsm[w] = v;
    __syncthreads();
    float s = 0.f;
    #pragma unroll
    for (int q = 0; q < 16; q++) s += redsm[q];
    return s;
}

__global__ void __launch_bounds__(512) topk_kernel(
    const float* __restrict__ epl,   // [B,N,N]
    float* __restrict__ out_ep)      // [B,N,N] in/out
{
    __shared__ unsigned long long keys[NN];
    __shared__ float vals[NN];
    __shared__ float redsm[16];

    const int row = blockIdx.x;
    const int i = row & (NN - 1);
    const int tid = threadIdx.x;
    const long rowbase = (long)row * NN;

    float v = out_ep[rowbase + tid];
    vals[tid] = v;
    float el = epl[rowbase + tid];
    if (tid == i) el = 0.f;
    float ep_last_sum = blockSum512(el, redsm);

    // key: (value bits asc, then prefer lower index among equals -> larger key)
    unsigned long long mykey =
        ((unsigned long long)__float_as_uint(v) << 32) | (unsigned)(NN - 1 - tid);
    keys[tid] = mykey;
    __syncthreads();

    // Bitonic sort ascending (512 elements, 512 threads)
    for (int k = 2; k <= NN; k <<= 1) {
        for (int j = k >> 1; j > 0; j >>= 1) {
            int ixj = tid ^ j;
            if (ixj > tid) {
                unsigned long long a = keys[tid];
                unsigned long long c = keys[ixj];
                bool asc = ((tid & k) == 0);
                if (asc ? (a > c) : (a < c)) {
                    keys[tid] = c;
                    keys[ixj] = a;
                }
            }
            __syncthreads();
        }
    }
    unsigned long long thr = keys[DROPK];   // 460th largest
    bool keep = (mykey >= thr);
    float kv = keep ? v : 0.f;

    float l1 = blockSum512(kv, redsm);
    l1 = fmaxf(l1, 1e-12f);
    float o = kv / l1 * ep_last_sum;
    o += ((tid == i) ? 1.f : 0.f) + 1e-6f;
    float rs = blockSum512(o, redsm);
    out_ep[rowbase + tid] = o / rs;
}

extern "C" void kernel_launch(void* const* d_in, const int* in_sizes, int n_in,
                              void* d_out, int out_size) {
    const float* vp  = (const float*)d_in[0];
    const float* epl = (const float*)d_in[1];
    const float* W1  = (const float*)d_in[2];
    const float* g1  = (const float*)d_in[3];
    const float* be1 = (const float*)d_in[4];
    const float* m1  = (const float*)d_in[5];
    const float* v1  = (const float*)d_in[6];
    const float* W2  = (const float*)d_in[7];
    const float* g2  = (const float*)d_in[8];
    const float* be2 = (const float*)d_in[9];
    const float* m2  = (const float*)d_in[10];
    const float* v2  = (const float*)d_in[11];
    const float* W3  = (const float*)d_in[12];
    const float* b3  = (const float*)d_in[13];

    float* out_ep = (float*)d_out;                    // [2,512,512]
    float* out_ns = (float*)d_out + NB * NN * NN;     // [2,512,512]

    cudaFuncSetAttribute(mlp_kernel, cudaFuncAttributeMaxDynamicSharedMemorySize,
                         SMEM_A_BYTES);

    prelude_kernel<<<1, 256>>>(W1, g1, be1, m1, v1, W2, g2, be2, m2, v2, W3, b3);
    mlp_kernel<<<NB * NN, 256, SMEM_A_BYTES>>>(vp, epl, out_ep, out_ns);
    topk_kernel<<<NB * NN, 512>>>(epl, out_ep);
}

// round 2
// speedup vs baseline: 1.0162x; 1.0162x over previous
#include <cuda_runtime.h>
#include <math.h>

// Problem constants (fixed shapes from reference): B=2, N=512, C=128, BC=64
#define NB 2
#define NN 512
#define NC 128
#define O1 128
#define O2 64
#define JC 64            // j-chunk per iteration
#define DROPK 52         // 512 - 460

// ---- packed f32x2 helpers (FFMA2 SASS, sm_103a) ----
#define PACKDUP(dst, s)      asm("mov.b64 %0, {%1, %1};" : "=l"(dst) : "f"(s))
#define PACK2(dst, lo, hi)   asm("mov.b64 %0, {%1, %2};" : "=l"(dst) : "f"(lo), "f"(hi))
#define UNPACK2(lo, hi, src) asm("mov.b64 {%0, %1}, %2;" : "=f"(lo), "=f"(hi) : "l"(src))
#define FMA2(acc, a, b)      asm("fma.rn.f32x2 %0, %1, %2, %0;" : "+l"(acc) : "l"(a), "l"(b))

// Folded weights (BN folded in), produced by prelude kernel.
__device__ float g_W1tf[NC * O1];   // [c][o]  : W1[o][c]*s1[o]
__device__ float g_W2tf[O1 * O2];   // [k][n]  : W2[n][k]*s2[n]
__device__ float g_b1f[O1];
__device__ float g_b2f[O2];
__device__ float g_W3f[O2];
__device__ float g_b3f;

__global__ void prelude_kernel(
    const float* __restrict__ W1, const float* __restrict__ g1,
    const float* __restrict__ be1, const float* __restrict__ m1,
    const float* __restrict__ v1,
    const float* __restrict__ W2, const float* __restrict__ g2,
    const float* __restrict__ be2, const float* __restrict__ m2,
    const float* __restrict__ v2,
    const float* __restrict__ W3, const float* __restrict__ b3)
{
    __shared__ float s1[O1], s2[O2];
    int t = threadIdx.x;
    if (t < O1) {
        float s = g1[t] / sqrtf(v1[t] + 1e-5f);
        s1[t] = s;
        if (blockIdx.x == 0) g_b1f[t] = be1[t] - m1[t] * s;
    } else if (t < O1 + O2) {
        int o = t - O1;
        float s = g2[o] / sqrtf(v2[o] + 1e-5f);
        s2[o] = s;
        if (blockIdx.x == 0) g_b2f[o] = be2[o] - m2[o] * s;
    } else if (t < O1 + 2 * O2) {
        int o = t - (O1 + O2);
        if (blockIdx.x == 0) {
            g_W3f[o] = W3[o];
            if (o == 0) g_b3f = b3[0];
        }
    }
    __syncthreads();
    int stride = blockDim.x * gridDim.x;
    int base = blockIdx.x * blockDim.x + t;
    for (int idx = base; idx < NC * O1; idx += stride) {
        int o = idx & (O1 - 1);
        int c = idx >> 7;
        g_W1tf[idx] = W1[o * NC + c] * s1[o];
    }
    for (int idx = base; idx < O1 * O2; idx += stride) {
        int n = idx & (O2 - 1);
        int k = idx >> 6;
        g_W2tf[idx] = W2[n * O1 + k] * s2[n];
    }
}

// SMEM layout (floats). Strides of 66 keep float2/u64 loads 8B-aligned.
#define SM_W1   0
#define SM_W2   (SM_W1 + NC * O1)            // 16384
#define SM_DS   (SM_W2 + O1 * O2)            // 24576
#define DS_STR  66
#define SM_H1   (SM_DS + NC * DS_STR)        // 33024
#define H1_STR  66
#define SM_VI   (SM_H1 + O1 * H1_STR)        // 41472
#define SM_RED  (SM_VI + NC)                 // 41600
#define RED_STR 65
#define SM_NSS  (SM_RED + 16 * RED_STR)      // 42640
#define SM_B1   (SM_NSS + JC)                // 42704
#define SM_B2   (SM_B1 + O1)                 // 42832
#define SM_W3   (SM_B2 + O2)                 // 42896
#define SM_TOTF (SM_W3 + O2)
#define SMEM_A_BYTES (SM_TOTF * 4)

__global__ void __launch_bounds__(256, 1) mlp_kernel(
    const float* __restrict__ vp,       // [B,N,C]
    const float* __restrict__ epl,      // [B,N,N]
    float* __restrict__ out_ep,         // [B,N,N] (raw: sigmoid(logit)*ep_last)
    float* __restrict__ out_ns)         // [B,N,N]
{
    extern __shared__ float sm[];
    const int row = blockIdx.x;         // 0..B*N-1
    const int b = row >> 9;
    const int i = row & (NN - 1);
    const int tid = threadIdx.x;

    float* W1s = sm + SM_W1;
    float* W2s = sm + SM_W2;
    float* Ds  = sm + SM_DS;
    float* H1s = sm + SM_H1;
    float* vis = sm + SM_VI;
    float* red = sm + SM_RED;
    float* nss = sm + SM_NSS;
    float* b1s = sm + SM_B1;
    float* b2s = sm + SM_B2;
    float* w3s = sm + SM_W3;

    // Stage weights once per block
    for (int idx = tid; idx < NC * O1; idx += 256) W1s[idx] = g_W1tf[idx];
    for (int idx = tid; idx < O1 * O2; idx += 256) W2s[idx] = g_W2tf[idx];
    if (tid < O1) {
        b1s[tid] = g_b1f[tid];
        vis[tid] = vp[(b * NN + i) * NC + tid];
    } else if (tid < O1 + O2) {
        int o = tid - O1;
        b2s[o] = g_b2f[o];
        w3s[o] = g_W3f[o];
    }

    const int ni  = tid & 15;   // GEMM1: 8 outputs o = ni*8.. (4 packed pairs)
    const int mi  = tid >> 4;   // GEMM1: 4 j's    m = mi*4..
    const int ni2 = tid & 15;   // GEMM2: 4 outputs n = ni2*4.. (2 packed pairs)
    const int mi2 = tid >> 4;   // GEMM2: 4 j's    m = mi2*4..

    const long rowbase = (long)row * NN;
    const float b3f = g_b3f;

    for (int jc = 0; jc < NN / JC; jc++) {
        const int j0 = jc * JC;
        __syncthreads();  // previous-chunk epilogue done; Ds/H1s/red/nss free

        // Build Ds[c][j] = (vi[c]-vj[c])^2
        #pragma unroll
        for (int t = 0; t < (JC * NC) / 256; t++) {
            int idx = t * 256 + tid;
            int j = idx >> 7;
            int c = idx & (NC - 1);
            float v = vp[(b * NN + j0 + j) * NC + c];
            float d = vis[c] - v;
            Ds[c * DS_STR + j] = d * d;
        }
        __syncthreads();

        // ---- GEMM1: H1[j][o] = leaky( D[j][:] . W1t[:][o] + b1 ) ----
        unsigned long long acc[4][4];   // [m][opair]
        {
            unsigned long long bp[4];
            #pragma unroll
            for (int np = 0; np < 4; np++)
                PACK2(bp[np], b1s[ni * 8 + 2 * np], b1s[ni * 8 + 2 * np + 1]);
            #pragma unroll
            for (int m = 0; m < 4; m++)
                #pragma unroll
                for (int np = 0; np < 4; np++)
                    acc[m][np] = bp[np];
        }

        #pragma unroll 4
        for (int k = 0; k < NC; k++) {
            const float2* dp = (const float2*)&Ds[k * DS_STR + mi * 4];
            float2 a01 = dp[0], a23 = dp[1];
            unsigned long long aa[4];
            PACKDUP(aa[0], a01.x); PACKDUP(aa[1], a01.y);
            PACKDUP(aa[2], a23.x); PACKDUP(aa[3], a23.y);
            const ulonglong2* wp = (const ulonglong2*)&W1s[k * O1 + ni * 8];
            ulonglong2 bA = wp[0], bB = wp[1];
            unsigned long long bv0 = bA.x, bv1 = bA.y, bv2 = bB.x, bv3 = bB.y;
            #pragma unroll
            for (int m = 0; m < 4; m++) {
                FMA2(acc[m][0], aa[m], bv0);
                FMA2(acc[m][1], aa[m], bv1);
                FMA2(acc[m][2], aa[m], bv2);
                FMA2(acc[m][3], aa[m], bv3);
            }
        }
        // epilogue: unpack, leaky, store K-major H1s[o][j]
        #pragma unroll
        for (int np = 0; np < 4; np++) {
            int o = ni * 8 + 2 * np;
            #pragma unroll
            for (int m = 0; m < 4; m++) {
                float lo, hi;
                UNPACK2(lo, hi, acc[m][np]);
                lo = (lo > 0.f) ? lo : 0.01f * lo;
                hi = (hi > 0.f) ? hi : 0.01f * hi;
                H1s[o * H1_STR + mi * 4 + m] = lo;
                H1s[(o + 1) * H1_STR + mi * 4 + m] = hi;
            }
        }
        __syncthreads();

        // ---- GEMM2 + layer3 fold ----
        unsigned long long acc2[4][2];
        {
            unsigned long long bp2[2];
            PACK2(bp2[0], b2s[ni2 * 4 + 0], b2s[ni2 * 4 + 1]);
            PACK2(bp2[1], b2s[ni2 * 4 + 2], b2s[ni2 * 4 + 3]);
            #pragma unroll
            for (int m = 0; m < 4; m++) {
                acc2[m][0] = bp2[0];
                acc2[m][1] = bp2[1];
            }
        }

        #pragma unroll 4
        for (int k = 0; k < O1; k++) {
            const float2* hp = (const float2*)&H1s[k * H1_STR + mi2 * 4];
            float2 a01 = hp[0], a23 = hp[1];
            unsigned long long aa[4];
            PACKDUP(aa[0], a01.x); PACKDUP(aa[1], a01.y);
            PACKDUP(aa[2], a23.x); PACKDUP(aa[3], a23.y);
            ulonglong2 wq = *(const ulonglong2*)&W2s[k * O2 + ni2 * 4];
            unsigned long long bv0 = wq.x, bv1 = wq.y;
            #pragma unroll
            for (int m = 0; m < 4; m++) {
                FMA2(acc2[m][0], aa[m], bv0);
                FMA2(acc2[m][1], aa[m], bv1);
            }
        }
        // leaky + dot with W3 -> partial logits
        float lp[4] = {0.f, 0.f, 0.f, 0.f};
        #pragma unroll
        for (int np = 0; np < 2; np++) {
            float wlo = w3s[ni2 * 4 + 2 * np];
            float whi = w3s[ni2 * 4 + 2 * np + 1];
            #pragma unroll
            for (int m = 0; m < 4; m++) {
                float lo, hi;
                UNPACK2(lo, hi, acc2[m][np]);
                lo = (lo > 0.f) ? lo : 0.01f * lo;
                hi = (hi > 0.f) ? hi : 0.01f * hi;
                lp[m] = fmaf(lo, wlo, lp[m]);
                lp[m] = fmaf(hi, whi, lp[m]);
            }
        }
        #pragma unroll
        for (int m = 0; m < 4; m++)
            red[ni2 * RED_STR + mi2 * 4 + m] = lp[m];

        // node similarity partial: column sums of Ds
        if (tid < JC) {
            float s = 0.f;
            #pragma unroll 8
            for (int c = 0; c < NC; c++) s += Ds[c * DS_STR + tid];
            nss[tid] = s;
        }
        __syncthreads();

        // epilogue: reduce logits, sigmoid, * ep_last, write
        if (tid < JC) {
            float lg = b3f;
            #pragma unroll
            for (int g = 0; g < 16; g++) lg += red[g * RED_STR + tid];
            float sg = 1.f / (1.f + expf(-lg));
            int jg = j0 + tid;
            float el = epl[rowbase + jg];
            if (jg == i) el = 0.f;
            out_ep[rowbase + jg] = sg * el;
            out_ns[rowbase + jg] = -nss[tid];
        }
    }
}

// ---------------- Kernel B: per-row top-k + normalize ----------------

__device__ __forceinline__ float blockSum512(float v, float* redsm) {
    #pragma unroll
    for (int o = 16; o > 0; o >>= 1) v += __shfl_xor_sync(0xffffffffu, v, o);
    int w = threadIdx.x >> 5;
    __syncthreads();
    if ((threadIdx.x & 31) == 0) redsm[w] = v;
    __syncthreads();
    float s = 0.f;
    #pragma unroll
    for (int q = 0; q < 16; q++) s += redsm[q];
    return s;
}

__global__ void __launch_bounds__(512) topk_kernel(
    const float* __restrict__ epl,   // [B,N,N]
    float* __restrict__ out_ep)      // [B,N,N] in/out
{
    __shared__ unsigned long long keys[NN];
    __shared__ float redsm[16];

    const int row = blockIdx.x;
    const int i = row & (NN - 1);
    const int tid = threadIdx.x;
    const long rowbase = (long)row * NN;

    float v = out_ep[rowbase + tid];
    float el = epl[rowbase + tid];
    if (tid == i) el = 0.f;
    float ep_last_sum = blockSum512(el, redsm);

    // key: (value bits asc, then prefer lower index among equals -> larger key)
    unsigned long long mykey =
        ((unsigned long long)__float_as_uint(v) << 32) | (unsigned)(NN - 1 - tid);
    keys[tid] = mykey;
    __syncthreads();

    // Bitonic sort ascending (512 elements, 512 threads)
    for (int k = 2; k <= NN; k <<= 1) {
        for (int j = k >> 1; j > 0; j >>= 1) {
            int ixj = tid ^ j;
            if (ixj > tid) {
                unsigned long long a = keys[tid];
                unsigned long long c = keys[ixj];
                bool asc = ((tid & k) == 0);
                if (asc ? (a > c) : (a < c)) {
                    keys[tid] = c;
                    keys[ixj] = a;
                }
            }
            __syncthreads();
        }
    }
    unsigned long long thr = keys[DROPK];   // 460th largest
    bool keep = (mykey >= thr);
    float kv = keep ? v : 0.f;

    float l1 = blockSum512(kv, redsm);
    l1 = fmaxf(l1, 1e-12f);
    float o = kv / l1 * ep_last_sum;
    o += ((tid == i) ? 1.f : 0.f) + 1e-6f;
    float rs = blockSum512(o, redsm);
    out_ep[rowbase + tid] = o / rs;
}

extern "C" void kernel_launch(void* const* d_in, const int* in_sizes, int n_in,
                              void* d_out, int out_size) {
    const float* vp  = (const float*)d_in[0];
    const float* epl = (const float*)d_in[1];
    const float* W1  = (const float*)d_in[2];
    const float* g1  = (const float*)d_in[3];
    const float* be1 = (const float*)d_in[4];
    const float* m1  = (const float*)d_in[5];
    const float* v1  = (const float*)d_in[6];
    const float* W2  = (const float*)d_in[7];
    const float* g2  = (const float*)d_in[8];
    const float* be2 = (const float*)d_in[9];
    const float* m2  = (const float*)d_in[10];
    const float* v2  = (const float*)d_in[11];
    const float* W3  = (const float*)d_in[12];
    const float* b3  = (const float*)d_in[13];

    float* out_ep = (float*)d_out;                    // [2,512,512]
    float* out_ns = (float*)d_out + NB * NN * NN;     // [2,512,512]

    cudaFuncSetAttribute(mlp_kernel, cudaFuncAttributeMaxDynamicSharedMemorySize,
                         SMEM_A_BYTES);

    prelude_kernel<<<32, 256>>>(W1, g1, be1, m1, v1, W2, g2, be2, m2, v2, W3, b3);
    mlp_kernel<<<NB * NN, 256, SMEM_A_BYTES>>>(vp, epl, out_ep, out_ns);
    topk_kernel<<<NB * NN, 512>>>(epl, out_ep);
}

// round 4
// speedup vs baseline: 2.7627x; 2.7187x over previous
#include <cuda_runtime.h>
#include <cuda_bf16.h>
#include <math.h>
#include <stdint.h>

#define NB 2
#define NN 512
#define NC 128
#define O1 128
#define O2 64
#define DROPK 52         // 512 - 460
#define SW 68            // row stride in u32 words (136 bf16 = 272B; conflict-free)

// Split two fp32 into packed bf16x2 hi-parts and packed bf16x2 lo-residuals.
__device__ __forceinline__ void split2(float x0, float x1, uint32_t& hp, uint32_t& lp) {
    asm("cvt.rn.bf16x2.f32 %0, %1, %2;" : "=r"(hp) : "f"(x1), "f"(x0));
    __nv_bfloat162 hb = *reinterpret_cast<__nv_bfloat162*>(&hp);
    float l0 = x0 - __bfloat162float(hb.x);
    float l1 = x1 - __bfloat162float(hb.y);
    asm("cvt.rn.bf16x2.f32 %0, %1, %2;" : "=r"(lp) : "f"(l1), "f"(l0));
}

__device__ __forceinline__ void mma16816(float* c, const uint32_t* a, const uint32_t* b) {
    asm volatile(
        "mma.sync.aligned.m16n8k16.row.col.f32.bf16.bf16.f32 "
        "{%0,%1,%2,%3}, {%4,%5,%6,%7}, {%8,%9}, {%0,%1,%2,%3};"
        : "+f"(c[0]), "+f"(c[1]), "+f"(c[2]), "+f"(c[3])
        : "r"(a[0]), "r"(a[1]), "r"(a[2]), "r"(a[3]), "r"(b[0]), "r"(b[1]));
}

// ---------------- folded + packed weights (prelude output) ----------------
// u32 words of bf16x2 pairs, layout [row][kpair] with row stride SW words.
__device__ uint32_t g_w1h[O1 * SW];
__device__ uint32_t g_w1l[O1 * SW];
__device__ uint32_t g_w2h[O2 * SW];
__device__ uint32_t g_w2l[O2 * SW];
__device__ float g_b1f[O1];
__device__ float g_b2f[O2];
__device__ float g_W3f[O2];
__device__ float g_b3f;

__global__ void prelude_kernel(
    const float* __restrict__ W1, const float* __restrict__ g1,
    const float* __restrict__ be1, const float* __restrict__ m1,
    const float* __restrict__ v1,
    const float* __restrict__ W2, const float* __restrict__ g2,
    const float* __restrict__ be2, const float* __restrict__ m2,
    const float* __restrict__ v2,
    const float* __restrict__ W3, const float* __restrict__ b3)
{
    __shared__ float s1[O1], s2[O2];
    int t = threadIdx.x;
    if (t < O1) {
        float s = g1[t] / sqrtf(v1[t] + 1e-5f);
        s1[t] = s;
        if (blockIdx.x == 0) g_b1f[t] = be1[t] - m1[t] * s;
    } else if (t < O1 + O2) {
        int o = t - O1;
        float s = g2[o] / sqrtf(v2[o] + 1e-5f);
        s2[o] = s;
        if (blockIdx.x == 0) g_b2f[o] = be2[o] - m2[o] * s;
    } else if (t < O1 + 2 * O2) {
        int o = t - (O1 + O2);
        if (blockIdx.x == 0) {
            g_W3f[o] = W3[o];
            if (o == 0) g_b3f = b3[0];
        }
    }
    __syncthreads();
    int stride = blockDim.x * gridDim.x;
    int base = blockIdx.x * blockDim.x + t;
    for (int idx = base; idx < O1 * 64; idx += stride) {
        int o = idx >> 6, cp = idx & 63;
        float v0 = W1[o * NC + 2 * cp] * s1[o];
        float v1v = W1[o * NC + 2 * cp + 1] * s1[o];
        uint32_t hp, lp;
        split2(v0, v1v, hp, lp);
        g_w1h[o * SW + cp] = hp;
        g_w1l[o * SW + cp] = lp;
    }
    for (int idx = base; idx < O2 * 64; idx += stride) {
        int n = idx >> 6, cp = idx & 63;
        float v0 = W2[n * O1 + 2 * cp] * s2[n];
        float v1v = W2[n * O1 + 2 * cp + 1] * s2[n];
        uint32_t hp, lp;
        split2(v0, v1v, hp, lp);
        g_w2h[n * SW + cp] = hp;
        g_w2l[n * SW + cp] = lp;
    }
}

// ---------------- SMEM layout (u32 word offsets) ----------------
#define WOFF_VIS  0                       // 128 f32
#define WOFF_B1   128                     // 128
#define WOFF_B2   256                     // 64
#define WOFF_W3   320                     // 64
#define WOFF_B3   384                     // 1 (+pad 3)
#define WOFF_RED  388                     // 4*128 = 512
#define WOFF_W1H  900
#define WOFF_W1L  (WOFF_W1H + O1 * SW)    // +8704
#define WOFF_W2H  (WOFF_W1L + O1 * SW)
#define WOFF_W2L  (WOFF_W2H + O2 * SW)    // +4352
#define WOFF_DH   (WOFF_W2L + O2 * SW)    // D tile hi (reused as H1 hi)
#define WOFF_DL   (WOFF_DH + 128 * SW)    // +8704
#define WTOT      (WOFF_DL + 128 * SW)
#define SMEM_TOTAL (WTOT * 4)             // ~175 KB

__global__ void __launch_bounds__(256, 1) mlp_kernel(
    const float* __restrict__ vp,       // [B,N,C]
    const float* __restrict__ epl,      // [B,N,N]
    float* __restrict__ out_ep,         // [B,N,N]
    float* __restrict__ out_ns)         // [B,N,N]
{
    extern __shared__ __align__(16) uint32_t smw[];
    const int tid = threadIdx.x;
    const int wid = tid >> 5;
    const int lid = tid & 31;
    const int g = lid >> 2;      // groupID 0..7
    const int tg = lid & 3;      // threadInGroup 0..3
    const int mBase = (wid >> 2) * 64;   // 0 or 64
    const int nq = wid & 3;              // n-quarter

    const int row = blockIdx.x;
    const int b = row >> 9;
    const int i = row & (NN - 1);
    const size_t rowbase = (size_t)row * NN;

    float* vis = (float*)(smw + WOFF_VIS);
    float* b1s = (float*)(smw + WOFF_B1);
    float* b2s = (float*)(smw + WOFF_B2);
    float* w3s = (float*)(smw + WOFF_W3);
    float* red = (float*)(smw + WOFF_RED);
    uint32_t* w1h = smw + WOFF_W1H;
    uint32_t* w1l = smw + WOFF_W1L;
    uint32_t* w2h = smw + WOFF_W2H;
    uint32_t* w2l = smw + WOFF_W2L;
    uint32_t* dh = smw + WOFF_DH;
    uint32_t* dl = smw + WOFF_DL;

    // ---- stage weights + scalars ----
    {
        uint4* d = (uint4*)w1h;
        const uint4* s = (const uint4*)g_w1h;
        for (int q = tid; q < O1 * SW / 4; q += 256) d[q] = s[q];
        d = (uint4*)w1l; s = (const uint4*)g_w1l;
        for (int q = tid; q < O1 * SW / 4; q += 256) d[q] = s[q];
        d = (uint4*)w2h; s = (const uint4*)g_w2h;
        for (int q = tid; q < O2 * SW / 4; q += 256) d[q] = s[q];
        d = (uint4*)w2l; s = (const uint4*)g_w2l;
        for (int q = tid; q < O2 * SW / 4; q += 256) d[q] = s[q];
    }
    if (tid < NC) {
        vis[tid] = vp[((size_t)(b * NN + i)) * NC + tid];
        b1s[tid] = g_b1f[tid];
    } else if (tid < NC + O2) {
        int o = tid - NC;
        b2s[o] = g_b2f[o];
        w3s[o] = g_W3f[o];
        if (o == 0) ((float*)(smw + WOFF_B3))[0] = g_b3f;
    }
    __syncthreads();
    const float b3f = ((float*)(smw + WOFF_B3))[0];

    for (int t = 0; t < 4; t++) {
        const int j0 = t * 128;

        // ---- build D tile (sqdiff -> bf16 hi/lo) + node similarity ----
        {
            const int j = tid >> 1;
            const int ch = tid & 1;
            const float4* v4 =
                (const float4*)(vp + ((size_t)(b * NN + j0 + j)) * NC + ch * 64);
            float ns = 0.f;
            #pragma unroll
            for (int q = 0; q < 16; q++) {
                float4 v = v4[q];
                int c = ch * 64 + q * 4;
                float d0 = vis[c] - v.x,     d1 = vis[c + 1] - v.y;
                float d2 = vis[c + 2] - v.z, d3 = vis[c + 3] - v.w;
                float s0 = d0 * d0, s1 = d1 * d1, s2 = d2 * d2, s3 = d3 * d3;
                ns += (s0 + s1) + (s2 + s3);
                uint32_t h0, l0, h1, l1;
                split2(s0, s1, h0, l0);
                split2(s2, s3, h1, l1);
                int wbase = j * SW + (c >> 1);
                *(uint2*)&dh[wbase] = make_uint2(h0, h1);
                *(uint2*)&dl[wbase] = make_uint2(l0, l1);
            }
            ns += __shfl_xor_sync(0xffffffffu, ns, 1);
            if (ch == 0) out_ns[rowbase + j0 + j] = -ns;
        }
        __syncthreads();

        // ---- GEMM1: H1 = leaky(D . W1^T + b1)  via 3-pass bf16 mma ----
        float acc[4][4][4];
        #pragma unroll
        for (int mf = 0; mf < 4; mf++)
            #pragma unroll
            for (int nf = 0; nf < 4; nf++)
                #pragma unroll
                for (int q = 0; q < 4; q++) acc[mf][nf][q] = 0.f;

        #pragma unroll
        for (int k = 0; k < 8; k++) {
            uint32_t Ah[4][4], Al[4][4], Bh[4][2], Bl[4][2];
            #pragma unroll
            for (int mf = 0; mf < 4; mf++) {
                int w0 = (mBase + mf * 16 + g) * SW + tg + k * 8;
                Ah[mf][0] = dh[w0];            Al[mf][0] = dl[w0];
                Ah[mf][1] = dh[w0 + 8 * SW];   Al[mf][1] = dl[w0 + 8 * SW];
                Ah[mf][2] = dh[w0 + 4];        Al[mf][2] = dl[w0 + 4];
                Ah[mf][3] = dh[w0 + 8 * SW + 4]; Al[mf][3] = dl[w0 + 8 * SW + 4];
            }
            #pragma unroll
            for (int nf = 0; nf < 4; nf++) {
                int wb = (nq * 32 + nf * 8 + g) * SW + tg + k * 8;
                Bh[nf][0] = w1h[wb]; Bh[nf][1] = w1h[wb + 4];
                Bl[nf][0] = w1l[wb]; Bl[nf][1] = w1l[wb + 4];
            }
            #pragma unroll
            for (int mf = 0; mf < 4; mf++)
                #pragma unroll
                for (int nf = 0; nf < 4; nf++) {
                    mma16816(acc[mf][nf], Ah[mf], Bh[nf]);
                    mma16816(acc[mf][nf], Ah[mf], Bl[nf]);
                    mma16816(acc[mf][nf], Al[mf], Bh[nf]);
                }
        }
        __syncthreads();   // all reads of D done

        // ---- epilogue1: bias+leaky+split -> H1 (overwrites D buffers) ----
        #pragma unroll
        for (int mf = 0; mf < 4; mf++) {
            int r0 = mBase + mf * 16 + g;
            #pragma unroll
            for (int nf = 0; nf < 4; nf++) {
                int o = nq * 32 + nf * 8 + 2 * tg;
                float bb0 = b1s[o], bb1 = b1s[o + 1];
                float x0 = acc[mf][nf][0] + bb0;
                float x1 = acc[mf][nf][1] + bb1;
                float x2 = acc[mf][nf][2] + bb0;
                float x3 = acc[mf][nf][3] + bb1;
                x0 = (x0 > 0.f) ? x0 : 0.01f * x0;
                x1 = (x1 > 0.f) ? x1 : 0.01f * x1;
                x2 = (x2 > 0.f) ? x2 : 0.01f * x2;
                x3 = (x3 > 0.f) ? x3 : 0.01f * x3;
                uint32_t hp, lp;
                split2(x0, x1, hp, lp);
                int wa = r0 * SW + (o >> 1);
                dh[wa] = hp; dl[wa] = lp;
                split2(x2, x3, hp, lp);
                int wa2 = (r0 + 8) * SW + (o >> 1);
                dh[wa2] = hp; dl[wa2] = lp;
            }
        }
        __syncthreads();

        // ---- GEMM2: A2 . W2^T (3-pass) ----
        float acc2[4][2][4];
        #pragma unroll
        for (int mf = 0; mf < 4; mf++)
            #pragma unroll
            for (int nf = 0; nf < 2; nf++)
                #pragma unroll
                for (int q = 0; q < 4; q++) acc2[mf][nf][q] = 0.f;

        #pragma unroll
        for (int k = 0; k < 8; k++) {
            uint32_t Ah[4][4], Al[4][4], Bh[2][2], Bl[2][2];
            #pragma unroll
            for (int mf = 0; mf < 4; mf++) {
                int w0 = (mBase + mf * 16 + g) * SW + tg + k * 8;
                Ah[mf][0] = dh[w0];            Al[mf][0] = dl[w0];
                Ah[mf][1] = dh[w0 + 8 * SW];   Al[mf][1] = dl[w0 + 8 * SW];
                Ah[mf][2] = dh[w0 + 4];        Al[mf][2] = dl[w0 + 4];
                Ah[mf][3] = dh[w0 + 8 * SW + 4]; Al[mf][3] = dl[w0 + 8 * SW + 4];
            }
            #pragma unroll
            for (int nf = 0; nf < 2; nf++) {
                int wb = (nq * 16 + nf * 8 + g) * SW + tg + k * 8;
                Bh[nf][0] = w2h[wb]; Bh[nf][1] = w2h[wb + 4];
                Bl[nf][0] = w2l[wb]; Bl[nf][1] = w2l[wb + 4];
            }
            #pragma unroll
            for (int mf = 0; mf < 4; mf++)
                #pragma unroll
                for (int nf = 0; nf < 2; nf++) {
                    mma16816(acc2[mf][nf], Ah[mf], Bh[nf]);
                    mma16816(acc2[mf][nf], Ah[mf], Bl[nf]);
                    mma16816(acc2[mf][nf], Al[mf], Bh[nf]);
                }
        }

        // ---- epilogue2: bias+leaky+W3 dot, reduce, sigmoid * ep_last ----
        {
            float lgA[4], lgB[4];
            #pragma unroll
            for (int mf = 0; mf < 4; mf++) { lgA[mf] = 0.f; lgB[mf] = 0.f; }
            #pragma unroll
            for (int mf = 0; mf < 4; mf++)
                #pragma unroll
                for (int nf = 0; nf < 2; nf++) {
                    int o = nq * 16 + nf * 8 + 2 * tg;
                    float bb0 = b2s[o], bb1 = b2s[o + 1];
                    float w0 = w3s[o], w1v = w3s[o + 1];
                    float x0 = acc2[mf][nf][0] + bb0;
                    float x1 = acc2[mf][nf][1] + bb1;
                    float x2 = acc2[mf][nf][2] + bb0;
                    float x3 = acc2[mf][nf][3] + bb1;
                    x0 = (x0 > 0.f) ? x0 : 0.01f * x0;
                    x1 = (x1 > 0.f) ? x1 : 0.01f * x1;
                    x2 = (x2 > 0.f) ? x2 : 0.01f * x2;
                    x3 = (x3 > 0.f) ? x3 : 0.01f * x3;
                    lgA[mf] = fmaf(x0, w0, lgA[mf]);
                    lgA[mf] = fmaf(x1, w1v, lgA[mf]);
                    lgB[mf] = fmaf(x2, w0, lgB[mf]);
                    lgB[mf] = fmaf(x3, w1v, lgB[mf]);
                }
            #pragma unroll
            for (int mf = 0; mf < 4; mf++) {
                float a = lgA[mf], c = lgB[mf];
                a += __shfl_xor_sync(0xffffffffu, a, 1);
                a += __shfl_xor_sync(0xffffffffu, a, 2);
                c += __shfl_xor_sync(0xffffffffu, c, 1);
                c += __shfl_xor_sync(0xffffffffu, c, 2);
                if (tg == 0) {
                    int r0 = mBase + mf * 16 + g;
                    red[nq * 128 + r0] = a;
                    red[nq * 128 + r0 + 8] = c;
                }
            }
        }
        __syncthreads();

        if (tid < 128) {
            int j = tid;
            float lg = b3f + red[j] + red[128 + j] + red[256 + j] + red[384 + j];
            float sg = 1.f / (1.f + expf(-lg));
            int jg = j0 + j;
            float el = epl[rowbase + jg];
            if (jg == i) el = 0.f;
            out_ep[rowbase + jg] = sg * el;
        }
        __syncthreads();
    }
}

// ---------------- Kernel B: per-row top-k + normalize ----------------
__device__ __forceinline__ float blockSum512(float v, float* redsm) {
    #pragma unroll
    for (int o = 16; o > 0; o >>= 1) v += __shfl_xor_sync(0xffffffffu, v, o);
    int w = threadIdx.x >> 5;
    __syncthreads();
    if ((threadIdx.x & 31) == 0) redsm[w] = v;
    __syncthreads();
    float s = 0.f;
    #pragma unroll
    for (int q = 0; q < 16; q++) s += redsm[q];
    return s;
}

__global__ void __launch_bounds__(512) topk_kernel(
    const float* __restrict__ epl,
    float* __restrict__ out_ep)
{
    __shared__ unsigned long long keys[NN];
    __shared__ float redsm[16];

    const int row = blockIdx.x;
    const int i = row & (NN - 1);
    const int tid = threadIdx.x;
    const size_t rowbase = (size_t)row * NN;

    float v = out_ep[rowbase + tid];
    float el = epl[rowbase + tid];
    if (tid == i) el = 0.f;
    float ep_last_sum = blockSum512(el, redsm);

    unsigned long long mykey =
        ((unsigned long long)__float_as_uint(v) << 32) | (unsigned)(NN - 1 - tid);
    keys[tid] = mykey;
    __syncthreads();

    for (int k = 2; k <= NN; k <<= 1) {
        for (int j = k >> 1; j > 0; j >>= 1) {
            int ixj = tid ^ j;
            if (ixj > tid) {
                unsigned long long a = keys[tid];
                unsigned long long c = keys[ixj];
                bool asc = ((tid & k) == 0);
                if (asc ? (a > c) : (a < c)) {
                    keys[tid] = c;
                    keys[ixj] = a;
                }
            }
            __syncthreads();
        }
    }
    unsigned long long thr = keys[DROPK];
    float kv = (mykey >= thr) ? v : 0.f;

    float l1 = blockSum512(kv, redsm);
    l1 = fmaxf(l1, 1e-12f);
    float o = kv / l1 * ep_last_sum;
    o += ((tid == i) ? 1.f : 0.f) + 1e-6f;
    float rs = blockSum512(o, redsm);
    out_ep[rowbase + tid] = o / rs;
}

extern "C" void kernel_launch(void* const* d_in, const int* in_sizes, int n_in,
                              void* d_out, int out_size) {
    const float* vp  = (const float*)d_in[0];
    const float* epl = (const float*)d_in[1];
    const float* W1  = (const float*)d_in[2];
    const float* g1  = (const float*)d_in[3];
    const float* be1 = (const float*)d_in[4];
    const float* m1  = (const float*)d_in[5];
    const float* v1  = (const float*)d_in[6];
    const float* W2  = (const float*)d_in[7];
    const float* g2  = (const float*)d_in[8];
    const float* be2 = (const float*)d_in[9];
    const float* m2  = (const float*)d_in[10];
    const float* v2  = (const float*)d_in[11];
    const float* W3  = (const float*)d_in[12];
    const float* b3  = (const float*)d_in[13];

    float* out_ep = (float*)d_out;
    float* out_ns = (float*)d_out + NB * NN * NN;

    cudaFuncSetAttribute(mlp_kernel, cudaFuncAttributeMaxDynamicSharedMemorySize,
                         SMEM_TOTAL);

    prelude_kernel<<<32, 256>>>(W1, g1, be1, m1, v1, W2, g2, be2, m2, v2, W3, b3);
    mlp_kernel<<<NB * NN, 256, SMEM_TOTAL>>>(vp, epl, out_ep, out_ns);
    topk_kernel<<<NB * NN, 512>>>(epl, out_ep);
}